// round 11
// baseline (speedup 1.0000x reference)
#include <cuda_runtime.h>
#include <cuda_bf16.h>
#include <math.h>

__device__ float g_pen;
__device__ float g_cnt;
__device__ unsigned int g_done;

__device__ __forceinline__ float2 ldg_nc256_f2(const float* p) {
    float2 v;
    asm("ld.global.nc.L2::256B.v2.f32 {%0,%1}, [%2];"
        : "=f"(v.x), "=f"(v.y) : "l"(p));
    return v;
}
__device__ __forceinline__ float ldg_nc_f(const float* p) {
    float v;
    asm("ld.global.nc.L2::256B.f32 %0, [%1];" : "=f"(v) : "l"(p));
    return v;
}

// fmod(a,2)==0  <=>  a*0.5 == floor(a*0.5)  (exact; negatives + NaN correct).
__device__ __forceinline__ bool is_even_int(float a) {
    const float h = a * 0.5f;
    return h == floorf(h);
}

// Process 8 consecutive 32-row chunks whose loaded values are in v[0..7].
// head_after = activity of the first row AFTER chunk 7 (valid on all lanes),
// ok_after   = whether that neighbor exists.
__device__ __forceinline__ void process8(const float2* v, float head_after,
                                         bool ok_after, int lane,
                                         float m2, float m3, float is2, float is3,
                                         float& pen, float& cnt) {
    float a[8];
    #pragma unroll
    for (int c = 0; c < 8; c++) a[c] = (v[c].y - m3) * is3;

    float an[8];
    #pragma unroll
    for (int c = 0; c < 8; c++) an[c] = __shfl_down_sync(0xffffffffu, a[c], 1);
    #pragma unroll
    for (int c = 0; c < 7; c++) {
        const float h = __shfl_sync(0xffffffffu, a[c + 1], 0);
        if (lane == 31) an[c] = h;
    }
    if (lane == 31) an[7] = head_after;

    const bool last_ok = (lane != 31) || ok_after;

    #pragma unroll
    for (int c = 0; c < 8; c++) {
        const float d = (v[c].x - m2) * is2;
        if (d < 0.0f || d > 252.0f)      pen += 1.0f;
        if (a[c] < 0.0f || a[c] > 22.0f) pen += 1.0f;
        if (a[c] != 22.0f)               cnt += 1.0f;

        const bool hn = (c < 7) || last_ok;
        if (hn && is_even_int(a[c]) && (a[c] < 20.0f)
               && (an[c] != a[c] + 1.0f) && (an[c] != 22.0f))
            pen += 1.0f;
    }
}

// Persistent kernel: each warp owns contiguous 512-row tiles,
// 16 front-batched LDG.64s, processed in two halves of 8.
__global__ __launch_bounds__(256, 4)
void fused_penalty_kernel(const float* __restrict__ x,
                          const float* __restrict__ min_,
                          const float* __restrict__ scale_,
                          float* __restrict__ out,
                          int out_size,
                          long long nrows,
                          int nblocks) {
    const float m2 = __ldg(min_ + 2);
    const float m3 = __ldg(min_ + 3);
    const float is2 = 1.0f / __ldg(scale_ + 2);
    const float is3 = 1.0f / __ldg(scale_ + 3);

    const int lane = threadIdx.x & 31;
    const long long wid = (long long)blockIdx.x * 8 + (threadIdx.x >> 5);
    const long long nwarps = (long long)gridDim.x * 8;
    const long long ntiles = (nrows + 511) >> 9;

    float pen = 0.0f;
    float cnt = 0.0f;

    for (long long t = wid; t < ntiles; t += nwarps) {
        const long long base = t << 9;

        if (base + 512 <= nrows) {
            // ---- Full tile: 16 front-batched hinted loads ----
            float2 v[16];
            #pragma unroll
            for (int c = 0; c < 16; c++) {
                v[c] = ldg_nc256_f2(x + (base + 32LL * c + lane) * 8 + 2);
            }

            const bool have_nxt = (base + 512 < nrows);
            float nxt_a = 0.0f;
            if (lane == 31 && have_nxt) {
                nxt_a = (ldg_nc_f(x + (base + 512) * 8 + 3) - m3) * is3;
            }

            // Head of chunk 8 (first row of second half) for half-0 boundary.
            const float a8_0 = (v[8].y - m3) * is3;
            const float head8 = __shfl_sync(0xffffffffu, a8_0, 0);

            process8(v,     head8, true,     lane, m2, m3, is2, is3, pen, cnt);
            process8(v + 8, nxt_a, have_nxt, lane, m2, m3, is2, is3, pen, cnt);
        } else {
            // ---- Partial tail tile: predicated scalar path ----
            #pragma unroll
            for (int c = 0; c < 16; c++) {
                const long long i = base + 32LL * c + lane;
                const bool valid = (i < nrows);
                float d = 0.0f, a0 = 0.0f;
                if (valid) {
                    const float2 vv = *reinterpret_cast<const float2*>(x + i * 8 + 2);
                    d  = (vv.x - m2) * is2;
                    a0 = (vv.y - m3) * is3;
                }
                float an0 = __shfl_down_sync(0xffffffffu, a0, 1);
                const bool hn = valid && (i + 1 < nrows);
                if (lane == 31 && hn) {
                    an0 = (x[(i + 1) * 8 + 3] - m3) * is3;
                }
                if (valid) {
                    if (d < 0.0f || d > 252.0f)   pen += 1.0f;
                    if (a0 < 0.0f || a0 > 22.0f)  pen += 1.0f;
                    if (a0 != 22.0f)              cnt += 1.0f;
                }
                if (hn && is_even_int(a0) && (a0 < 20.0f)
                       && (an0 != a0 + 1.0f) && (an0 != 22.0f))
                    pen += 1.0f;
            }
        }
    }

    // ---- Warp reduction ----
    #pragma unroll
    for (int off = 16; off > 0; off >>= 1) {
        pen += __shfl_down_sync(0xffffffffu, pen, off);
        cnt += __shfl_down_sync(0xffffffffu, cnt, off);
    }

    __shared__ float s_pen[8];
    __shared__ float s_cnt[8];
    const int w = threadIdx.x >> 5;
    if (lane == 0) { s_pen[w] = pen; s_cnt[w] = cnt; }
    __syncthreads();

    if (threadIdx.x == 0) {
        float bp = 0.0f, bc = 0.0f;
        #pragma unroll
        for (int k = 0; k < 8; k++) { bp += s_pen[k]; bc += s_cnt[k]; }

        atomicAdd(&g_pen, bp);
        atomicAdd(&g_cnt, bc);
        __threadfence();

        const unsigned int ticket = atomicAdd(&g_done, 1u);
        if (ticket == (unsigned int)(nblocks - 1)) {
            const float p = atomicAdd(&g_pen, 0.0f);
            const float c = atomicAdd(&g_cnt, 0.0f);
            const float result = p + fabsf(c - 58.0f);
            for (int k = 0; k < out_size; k++) out[k] = result;
            g_pen = 0.0f;
            g_cnt = 0.0f;
            __threadfence();
            g_done = 0u;
        }
    }
}

extern "C" void kernel_launch(void* const* d_in, const int* in_sizes, int n_in,
                              void* d_out, int out_size) {
    const float* x      = (const float*)d_in[0];
    const float* min_   = (const float*)d_in[1];
    const float* scale_ = (const float*)d_in[2];
    float* out = (float*)d_out;

    const long long nrows = (long long)in_sizes[0] / 8;
    const long long ntiles = (nrows + 511) >> 9;

    // Persistent single wave: 4 blocks/SM * 148 SMs = 592 blocks.
    long long blocks_ll = 592;
    long long need = (ntiles + 7) / 8;
    if (need < 1) need = 1;
    if (need < blocks_ll) blocks_ll = need;
    const int blocks = (int)blocks_ll;

    fused_penalty_kernel<<<blocks, 256>>>(x, min_, scale_, out, out_size,
                                          nrows, blocks);
}

// round 12
// speedup vs baseline: 1.0082x; 1.0082x over previous
#include <cuda_runtime.h>
#include <cuda_bf16.h>
#include <math.h>

__device__ float g_pen;
__device__ float g_cnt;
__device__ unsigned int g_done;

// Non-coherent load with 256B L2 fetch-granule hint.
__device__ __forceinline__ float2 ldg_nc256_f2(const float* p) {
    float2 v;
    asm("ld.global.nc.L2::256B.v2.f32 {%0,%1}, [%2];"
        : "=f"(v.x), "=f"(v.y) : "l"(p));
    return v;
}
__device__ __forceinline__ float ldg_nc256_f(const float* p) {
    float v;
    asm("ld.global.nc.L2::256B.f32 %0, [%1];" : "=f"(v) : "l"(p));
    return v;
}

// fmod(a,2)==0  <=>  a*0.5 == floor(a*0.5)  (exact; negatives + NaN correct).
__device__ __forceinline__ bool is_even_int(float a) {
    const float h = a * 0.5f;
    return h == floorf(h);
}

// Persistent kernel: each warp loops over contiguous 256-row tiles.
__global__ __launch_bounds__(256)
void fused_penalty_kernel(const float* __restrict__ x,
                          const float* __restrict__ min_,
                          const float* __restrict__ scale_,
                          float* __restrict__ out,
                          int out_size,
                          long long nrows,
                          int nblocks) {
    const float m2 = __ldg(min_ + 2);
    const float m3 = __ldg(min_ + 3);
    const float is2 = 1.0f / __ldg(scale_ + 2);
    const float is3 = 1.0f / __ldg(scale_ + 3);

    const int lane = threadIdx.x & 31;
    const long long wid = (long long)blockIdx.x * 8 + (threadIdx.x >> 5);
    const long long nwarps = (long long)gridDim.x * 8;
    const long long ntiles = (nrows + 255) >> 8;

    float pen = 0.0f;
    float cnt = 0.0f;

    for (long long t = wid; t < ntiles; t += nwarps) {
        const long long base = t << 8;

        if (base + 256 <= nrows) {
            // ---- Full tile: 8 front-batched hinted loads ----
            float2 v[8];
            #pragma unroll
            for (int c = 0; c < 8; c++) {
                v[c] = ldg_nc256_f2(x + (base + 32LL * c + lane) * 8 + 2);
            }

            const bool have_nxt = (base + 256 < nrows);
            float nxt_a = 0.0f;
            if (lane == 31 && have_nxt) {
                nxt_a = (ldg_nc256_f(x + (base + 256) * 8 + 3) - m3) * is3;
            }

            float a[8];
            #pragma unroll
            for (int c = 0; c < 8; c++) a[c] = (v[c].y - m3) * is3;

            float an[8];
            #pragma unroll
            for (int c = 0; c < 8; c++)
                an[c] = __shfl_down_sync(0xffffffffu, a[c], 1);
            #pragma unroll
            for (int c = 0; c < 7; c++) {
                const float h = __shfl_sync(0xffffffffu, a[c + 1], 0);
                if (lane == 31) an[c] = h;
            }
            if (lane == 31) an[7] = nxt_a;

            const bool last_ok = (lane != 31) || have_nxt;

            #pragma unroll
            for (int c = 0; c < 8; c++) {
                const float d = (v[c].x - m2) * is2;
                if (d < 0.0f || d > 252.0f)      pen += 1.0f;
                if (a[c] < 0.0f || a[c] > 22.0f) pen += 1.0f;
                if (a[c] != 22.0f)               cnt += 1.0f;

                const bool hn = (c < 7) || last_ok;
                if (hn && is_even_int(a[c]) && (a[c] < 20.0f)
                       && (an[c] != a[c] + 1.0f) && (an[c] != 22.0f))
                    pen += 1.0f;
            }
        } else {
            // ---- Partial tail tile: predicated scalar path ----
            #pragma unroll
            for (int c = 0; c < 8; c++) {
                const long long i = base + 32LL * c + lane;
                const bool valid = (i < nrows);
                float d = 0.0f, a0 = 0.0f;
                if (valid) {
                    const float2 vv = *reinterpret_cast<const float2*>(x + i * 8 + 2);
                    d  = (vv.x - m2) * is2;
                    a0 = (vv.y - m3) * is3;
                }
                float an0 = __shfl_down_sync(0xffffffffu, a0, 1);
                const bool hn = valid && (i + 1 < nrows);
                if (lane == 31 && hn) {
                    an0 = (x[(i + 1) * 8 + 3] - m3) * is3;
                }
                if (valid) {
                    if (d < 0.0f || d > 252.0f)   pen += 1.0f;
                    if (a0 < 0.0f || a0 > 22.0f)  pen += 1.0f;
                    if (a0 != 22.0f)              cnt += 1.0f;
                }
                if (hn && is_even_int(a0) && (a0 < 20.0f)
                       && (an0 != a0 + 1.0f) && (an0 != 22.0f))
                    pen += 1.0f;
            }
        }
    }

    // ---- Warp reduction ----
    #pragma unroll
    for (int off = 16; off > 0; off >>= 1) {
        pen += __shfl_down_sync(0xffffffffu, pen, off);
        cnt += __shfl_down_sync(0xffffffffu, cnt, off);
    }

    __shared__ float s_pen[8];
    __shared__ float s_cnt[8];
    const int w = threadIdx.x >> 5;
    if (lane == 0) { s_pen[w] = pen; s_cnt[w] = cnt; }
    __syncthreads();

    if (threadIdx.x == 0) {
        float bp = 0.0f, bc = 0.0f;
        #pragma unroll
        for (int k = 0; k < 8; k++) { bp += s_pen[k]; bc += s_cnt[k]; }

        atomicAdd(&g_pen, bp);
        atomicAdd(&g_cnt, bc);
        __threadfence();

        const unsigned int ticket = atomicAdd(&g_done, 1u);
        if (ticket == (unsigned int)(nblocks - 1)) {
            const float p = atomicAdd(&g_pen, 0.0f);
            const float c = atomicAdd(&g_cnt, 0.0f);
            const float result = p + fabsf(c - 58.0f);
            for (int k = 0; k < out_size; k++) out[k] = result;
            g_pen = 0.0f;
            g_cnt = 0.0f;
            __threadfence();
            g_done = 0u;
        }
    }
}

extern "C" void kernel_launch(void* const* d_in, const int* in_sizes, int n_in,
                              void* d_out, int out_size) {
    const float* x      = (const float*)d_in[0];
    const float* min_   = (const float*)d_in[1];
    const float* scale_ = (const float*)d_in[2];
    float* out = (float*)d_out;

    const long long nrows = (long long)in_sizes[0] / 8;
    const long long ntiles = (nrows + 255) >> 8;

    // Persistent single wave: 5 blocks/SM * 148 SMs = 740 blocks.
    long long blocks_ll = 740;
    long long need = (ntiles + 7) / 8;   // one tile per warp minimum
    if (need < 1) need = 1;
    if (need < blocks_ll) blocks_ll = need;
    const int blocks = (int)blocks_ll;

    fused_penalty_kernel<<<blocks, 256>>>(x, min_, scale_, out, out_size,
                                          nrows, blocks);
}

// round 13
// speedup vs baseline: 1.0189x; 1.0106x over previous
#include <cuda_runtime.h>
#include <cuda_bf16.h>
#include <math.h>

__device__ float g_pen;
__device__ float g_cnt;
__device__ unsigned int g_done;

// Non-coherent load with 256B L2 fetch-granule hint.
__device__ __forceinline__ float2 ldg_nc256_f2(const float* p) {
    float2 v;
    asm("ld.global.nc.L2::256B.v2.f32 {%0,%1}, [%2];"
        : "=f"(v.x), "=f"(v.y) : "l"(p));
    return v;
}
__device__ __forceinline__ float ldg_nc256_f(const float* p) {
    float v;
    asm("ld.global.nc.L2::256B.f32 %0, [%1];" : "=f"(v) : "l"(p));
    return v;
}

// fmod(a,2)==0  <=>  a*0.5 == floor(a*0.5)  (exact; negatives + NaN correct).
__device__ __forceinline__ bool is_even_int(float a) {
    const float h = a * 0.5f;
    return h == floorf(h);
}

// Persistent kernel: each warp loops over contiguous 256-row tiles.
// 740 blocks (5/SM single wave), 8 front-batched LDG.64 per warp-tile,
// neighbor activity forwarded through registers (1 extra 4B load / 256 rows).
__global__ __launch_bounds__(256)
void fused_penalty_kernel(const float* __restrict__ x,
                          const float* __restrict__ min_,
                          const float* __restrict__ scale_,
                          float* __restrict__ out,
                          int out_size,
                          long long nrows,
                          int nblocks) {
    const float m2 = __ldg(min_ + 2);
    const float m3 = __ldg(min_ + 3);
    const float is2 = 1.0f / __ldg(scale_ + 2);
    const float is3 = 1.0f / __ldg(scale_ + 3);

    const int lane = threadIdx.x & 31;
    const long long wid = (long long)blockIdx.x * 8 + (threadIdx.x >> 5);
    const long long nwarps = (long long)gridDim.x * 8;
    const long long ntiles = (nrows + 255) >> 8;

    float pen = 0.0f;
    float cnt = 0.0f;

    for (long long t = wid; t < ntiles; t += nwarps) {
        const long long base = t << 8;

        if (base + 256 <= nrows) {
            // ---- Full tile: 8 front-batched hinted loads ----
            float2 v[8];
            #pragma unroll
            for (int c = 0; c < 8; c++) {
                v[c] = ldg_nc256_f2(x + (base + 32LL * c + lane) * 8 + 2);
            }

            const bool have_nxt = (base + 256 < nrows);
            float nxt_a = 0.0f;
            if (lane == 31 && have_nxt) {
                nxt_a = (ldg_nc256_f(x + (base + 256) * 8 + 3) - m3) * is3;
            }

            float a[8];
            #pragma unroll
            for (int c = 0; c < 8; c++) a[c] = (v[c].y - m3) * is3;

            float an[8];
            #pragma unroll
            for (int c = 0; c < 8; c++)
                an[c] = __shfl_down_sync(0xffffffffu, a[c], 1);
            #pragma unroll
            for (int c = 0; c < 7; c++) {
                const float h = __shfl_sync(0xffffffffu, a[c + 1], 0);
                if (lane == 31) an[c] = h;
            }
            if (lane == 31) an[7] = nxt_a;

            const bool last_ok = (lane != 31) || have_nxt;

            #pragma unroll
            for (int c = 0; c < 8; c++) {
                const float d = (v[c].x - m2) * is2;
                if (d < 0.0f || d > 252.0f)      pen += 1.0f;
                if (a[c] < 0.0f || a[c] > 22.0f) pen += 1.0f;
                if (a[c] != 22.0f)               cnt += 1.0f;

                const bool hn = (c < 7) || last_ok;
                if (hn && is_even_int(a[c]) && (a[c] < 20.0f)
                       && (an[c] != a[c] + 1.0f) && (an[c] != 22.0f))
                    pen += 1.0f;
            }
        } else {
            // ---- Partial tail tile: predicated scalar path ----
            #pragma unroll
            for (int c = 0; c < 8; c++) {
                const long long i = base + 32LL * c + lane;
                const bool valid = (i < nrows);
                float d = 0.0f, a0 = 0.0f;
                if (valid) {
                    const float2 vv = *reinterpret_cast<const float2*>(x + i * 8 + 2);
                    d  = (vv.x - m2) * is2;
                    a0 = (vv.y - m3) * is3;
                }
                float an0 = __shfl_down_sync(0xffffffffu, a0, 1);
                const bool hn = valid && (i + 1 < nrows);
                if (lane == 31 && hn) {
                    an0 = (x[(i + 1) * 8 + 3] - m3) * is3;
                }
                if (valid) {
                    if (d < 0.0f || d > 252.0f)   pen += 1.0f;
                    if (a0 < 0.0f || a0 > 22.0f)  pen += 1.0f;
                    if (a0 != 22.0f)              cnt += 1.0f;
                }
                if (hn && is_even_int(a0) && (a0 < 20.0f)
                       && (an0 != a0 + 1.0f) && (an0 != 22.0f))
                    pen += 1.0f;
            }
        }
    }

    // ---- Warp reduction ----
    #pragma unroll
    for (int off = 16; off > 0; off >>= 1) {
        pen += __shfl_down_sync(0xffffffffu, pen, off);
        cnt += __shfl_down_sync(0xffffffffu, cnt, off);
    }

    __shared__ float s_pen[8];
    __shared__ float s_cnt[8];
    const int w = threadIdx.x >> 5;
    if (lane == 0) { s_pen[w] = pen; s_cnt[w] = cnt; }
    __syncthreads();

    if (threadIdx.x == 0) {
        float bp = 0.0f, bc = 0.0f;
        #pragma unroll
        for (int k = 0; k < 8; k++) { bp += s_pen[k]; bc += s_cnt[k]; }

        atomicAdd(&g_pen, bp);
        atomicAdd(&g_cnt, bc);
        __threadfence();

        const unsigned int ticket = atomicAdd(&g_done, 1u);
        if (ticket == (unsigned int)(nblocks - 1)) {
            const float p = atomicAdd(&g_pen, 0.0f);
            const float c = atomicAdd(&g_cnt, 0.0f);
            const float result = p + fabsf(c - 58.0f);
            for (int k = 0; k < out_size; k++) out[k] = result;
            g_pen = 0.0f;
            g_cnt = 0.0f;
            __threadfence();
            g_done = 0u;
        }
    }
}

extern "C" void kernel_launch(void* const* d_in, const int* in_sizes, int n_in,
                              void* d_out, int out_size) {
    const float* x      = (const float*)d_in[0];
    const float* min_   = (const float*)d_in[1];
    const float* scale_ = (const float*)d_in[2];
    float* out = (float*)d_out;

    const long long nrows = (long long)in_sizes[0] / 8;
    const long long ntiles = (nrows + 255) >> 8;

    // Persistent single wave: 5 blocks/SM * 148 SMs = 740 blocks.
    long long blocks_ll = 740;
    long long need = (ntiles + 7) / 8;   // one tile per warp minimum
    if (need < 1) need = 1;
    if (need < blocks_ll) blocks_ll = need;
    const int blocks = (int)blocks_ll;

    fused_penalty_kernel<<<blocks, 256>>>(x, min_, scale_, out, out_size,
                                          nrows, blocks);
}

// round 14
// speedup vs baseline: 1.0201x; 1.0012x over previous
#include <cuda_runtime.h>
#include <cuda_bf16.h>
#include <math.h>

__device__ float g_pen;
__device__ float g_cnt;
__device__ unsigned int g_done;

// Non-coherent load with 256B L2 fetch-granule hint.
__device__ __forceinline__ float2 ldg_nc256_f2(const float* p) {
    float2 v;
    asm("ld.global.nc.L2::256B.v2.f32 {%0,%1}, [%2];"
        : "=f"(v.x), "=f"(v.y) : "l"(p));
    return v;
}
__device__ __forceinline__ float ldg_nc256_f(const float* p) {
    float v;
    asm("ld.global.nc.L2::256B.f32 %0, [%1];" : "=f"(v) : "l"(p));
    return v;
}

// fmod(a,2)==0  <=>  a*0.5 == floor(a*0.5)  (exact; negatives + NaN correct).
__device__ __forceinline__ bool is_even_int(float a) {
    const float h = a * 0.5f;
    return h == floorf(h);
}

// Persistent kernel: each warp loops over contiguous 256-row tiles.
// 740 blocks (5/SM single wave, 48 regs = regfile-limited optimum),
// 8 front-batched LDG.64 per warp-tile, neighbor activity forwarded
// through registers (1 extra 4B load per 256 rows).
__global__ __launch_bounds__(256)
void fused_penalty_kernel(const float* __restrict__ x,
                          const float* __restrict__ min_,
                          const float* __restrict__ scale_,
                          float* __restrict__ out,
                          int out_size,
                          long long nrows,
                          int nblocks) {
    const float m2 = __ldg(min_ + 2);
    const float m3 = __ldg(min_ + 3);
    const float is2 = 1.0f / __ldg(scale_ + 2);
    const float is3 = 1.0f / __ldg(scale_ + 3);

    const int lane = threadIdx.x & 31;
    const long long wid = (long long)blockIdx.x * 8 + (threadIdx.x >> 5);
    const long long nwarps = (long long)gridDim.x * 8;
    const long long ntiles = (nrows + 255) >> 8;

    float pen = 0.0f;
    float cnt = 0.0f;

    for (long long t = wid; t < ntiles; t += nwarps) {
        const long long base = t << 8;

        if (base + 256 <= nrows) {
            // ---- Full tile: 8 front-batched hinted loads ----
            float2 v[8];
            #pragma unroll
            for (int c = 0; c < 8; c++) {
                v[c] = ldg_nc256_f2(x + (base + 32LL * c + lane) * 8 + 2);
            }

            const bool have_nxt = (base + 256 < nrows);
            float nxt_a = 0.0f;
            if (lane == 31 && have_nxt) {
                nxt_a = (ldg_nc256_f(x + (base + 256) * 8 + 3) - m3) * is3;
            }

            float a[8];
            #pragma unroll
            for (int c = 0; c < 8; c++) a[c] = (v[c].y - m3) * is3;

            float an[8];
            #pragma unroll
            for (int c = 0; c < 8; c++)
                an[c] = __shfl_down_sync(0xffffffffu, a[c], 1);
            #pragma unroll
            for (int c = 0; c < 7; c++) {
                const float h = __shfl_sync(0xffffffffu, a[c + 1], 0);
                if (lane == 31) an[c] = h;
            }
            if (lane == 31) an[7] = nxt_a;

            const bool last_ok = (lane != 31) || have_nxt;

            #pragma unroll
            for (int c = 0; c < 8; c++) {
                const float d = (v[c].x - m2) * is2;
                if (d < 0.0f || d > 252.0f)      pen += 1.0f;
                if (a[c] < 0.0f || a[c] > 22.0f) pen += 1.0f;
                if (a[c] != 22.0f)               cnt += 1.0f;

                const bool hn = (c < 7) || last_ok;
                if (hn && is_even_int(a[c]) && (a[c] < 20.0f)
                       && (an[c] != a[c] + 1.0f) && (an[c] != 22.0f))
                    pen += 1.0f;
            }
        } else {
            // ---- Partial tail tile: predicated scalar path ----
            #pragma unroll
            for (int c = 0; c < 8; c++) {
                const long long i = base + 32LL * c + lane;
                const bool valid = (i < nrows);
                float d = 0.0f, a0 = 0.0f;
                if (valid) {
                    const float2 vv = *reinterpret_cast<const float2*>(x + i * 8 + 2);
                    d  = (vv.x - m2) * is2;
                    a0 = (vv.y - m3) * is3;
                }
                float an0 = __shfl_down_sync(0xffffffffu, a0, 1);
                const bool hn = valid && (i + 1 < nrows);
                if (lane == 31 && hn) {
                    an0 = (x[(i + 1) * 8 + 3] - m3) * is3;
                }
                if (valid) {
                    if (d < 0.0f || d > 252.0f)   pen += 1.0f;
                    if (a0 < 0.0f || a0 > 22.0f)  pen += 1.0f;
                    if (a0 != 22.0f)              cnt += 1.0f;
                }
                if (hn && is_even_int(a0) && (a0 < 20.0f)
                       && (an0 != a0 + 1.0f) && (an0 != 22.0f))
                    pen += 1.0f;
            }
        }
    }

    // ---- Warp reduction ----
    #pragma unroll
    for (int off = 16; off > 0; off >>= 1) {
        pen += __shfl_down_sync(0xffffffffu, pen, off);
        cnt += __shfl_down_sync(0xffffffffu, cnt, off);
    }

    __shared__ float s_pen[8];
    __shared__ float s_cnt[8];
    const int w = threadIdx.x >> 5;
    if (lane == 0) { s_pen[w] = pen; s_cnt[w] = cnt; }
    __syncthreads();

    if (threadIdx.x == 0) {
        float bp = 0.0f, bc = 0.0f;
        #pragma unroll
        for (int k = 0; k < 8; k++) { bp += s_pen[k]; bc += s_cnt[k]; }

        atomicAdd(&g_pen, bp);
        atomicAdd(&g_cnt, bc);
        __threadfence();

        const unsigned int ticket = atomicAdd(&g_done, 1u);
        if (ticket == (unsigned int)(nblocks - 1)) {
            const float p = atomicAdd(&g_pen, 0.0f);
            const float c = atomicAdd(&g_cnt, 0.0f);
            const float result = p + fabsf(c - 58.0f);
            for (int k = 0; k < out_size; k++) out[k] = result;
            g_pen = 0.0f;
            g_cnt = 0.0f;
            __threadfence();
            g_done = 0u;
        }
    }
}

extern "C" void kernel_launch(void* const* d_in, const int* in_sizes, int n_in,
                              void* d_out, int out_size) {
    const float* x      = (const float*)d_in[0];
    const float* min_   = (const float*)d_in[1];
    const float* scale_ = (const float*)d_in[2];
    float* out = (float*)d_out;

    const long long nrows = (long long)in_sizes[0] / 8;
    const long long ntiles = (nrows + 255) >> 8;

    // Persistent single wave: 5 blocks/SM * 148 SMs = 740 blocks.
    long long blocks_ll = 740;
    long long need = (ntiles + 7) / 8;   // one tile per warp minimum
    if (need < 1) need = 1;
    if (need < blocks_ll) blocks_ll = need;
    const int blocks = (int)blocks_ll;

    fused_penalty_kernel<<<blocks, 256>>>(x, min_, scale_, out, out_size,
                                          nrows, blocks);
}